// round 8
// baseline (speedup 1.0000x reference)
#include <cuda_runtime.h>
#include <cuda_bf16.h>
#include <cstdint>

// ---------------- problem constants ----------------
#define BATCH 64
#define NTOK  197
#define HEADS 12
#define HDIM  64
#define CDIM  768
#define CK    2304
#define MROWS (BATCH*NTOK) // 12608
#define NRD   732
#define NW    50
#define BHT   (BATCH*HEADS)

// ---------------- device scratch (cudaMalloc is banned) -------------
__device__ float              g_qkv[(size_t)MROWS * CK];
__device__ float              g_att[(size_t)MROWS * CDIM];
__device__ float              g_sq[BHT];
__device__ float              g_sk[BHT];
__device__ unsigned long long g_qb[BHT * NTOK];
__device__ unsigned long long g_kb[BHT * NTOK];
__device__ unsigned int       g_vT[(size_t)BHT * HDIM * NW];

// ---------------- small helpers ----------------
__device__ __forceinline__ int dp4a_us(unsigned int a, unsigned int b, int c) {
    int d; asm("dp4a.u32.s32 %0, %1, %2, %3;" : "=r"(d) : "r"(a), "r"(b), "r"(c));
    return d;
}
__device__ __forceinline__ void mma_bf16(float* c, const uint32_t* a, const uint32_t* b) {
    asm volatile(
        "mma.sync.aligned.m16n8k16.row.col.f32.bf16.bf16.f32 "
        "{%0,%1,%2,%3}, {%4,%5,%6,%7}, {%8,%9}, {%0,%1,%2,%3};"
        : "+f"(c[0]), "+f"(c[1]), "+f"(c[2]), "+f"(c[3])
        : "r"(a[0]), "r"(a[1]), "r"(a[2]), "r"(a[3]), "r"(b[0]), "r"(b[1]));
}
// Exact bf16 3-way split: x = s0 + s1 + s2 + O(2^-26 x); subtractions exact in fp32.
__device__ __forceinline__ void bsplit(float x, uint16_t& s0, uint16_t& s1, uint16_t& s2,
                                       bool need3) {
    __nv_bfloat16 h0 = __float2bfloat16(x);
    float f0 = __bfloat162float(h0);
    float r1 = x - f0;
    __nv_bfloat16 h1 = __float2bfloat16(r1);
    s0 = *reinterpret_cast<uint16_t*>(&h0);
    s1 = *reinterpret_cast<uint16_t*>(&h1);
    if (need3) {
        float r2 = r1 - __bfloat162float(h1);
        __nv_bfloat16 h2 = __float2bfloat16(r2);
        s2 = *reinterpret_cast<uint16_t*>(&h2);
    } else s2 = 0;
}

// ================= split-BF16 mma.sync GEMM, fp32 register drain =============
// C[M,N] = A[M,768] @ W[N,768]^T (+bias), leading dim ldc.
// S = bf16 split terms (2 or 3); P = products (3: 00,01,10 | 6: +02,20,11)
// KEY (R8): per k-tile the P products are chained into a ZERO-initialized
// fragment (partial sums stay small, so any reduced-precision mma accumulate
// rounds a small value), then drained into fp32 register accumulators with
// exact FADDs. Long-range accumulation never touches the mma C-path.
#define GK      768
#define TBM     128
#define TBN     128
#define TBK     16
#define KT      (GK / TBK)          // 48
#define RPAD    12                  // u32 per smem row (8 data + 4 pad)
#define TILEU   (128 * RPAD)        // u32 per tile

template<int S, int P>
__global__ void __launch_bounds__(256, 1) gemm_bf16s(
    const float* __restrict__ A, const float* __restrict__ W,
    const float* __restrict__ bias, float* __restrict__ C,
    int M, int ldc)
{
    extern __shared__ uint32_t smu[];
    auto tbase = [&](int buf, int mat, int t) -> uint32_t* {
        return smu + (size_t)(((buf * 2 + mat) * S) + t) * TILEU;
    };

    const int tid  = threadIdx.x;
    const int wid  = tid >> 5;
    const int lane = tid & 31;
    const int gq   = lane >> 2;             // 0..7
    const int tq   = lane & 3;              // 0..3
    const int bm = blockIdx.y * TBM;
    const int bn = blockIdx.x * TBN;
    const int wm = (wid >> 2) * 64;
    const int wn = (wid & 3) * 32;

    // ---- producer mapping: 1 row x 8 k-floats per matrix per thread ----
    const int prow = tid >> 1;              // 0..127
    const int kseg = tid & 1;               // 0/1 -> k offset 0/8
    int arow = bm + prow; if (arow >= M) arow = M - 1;
    const float* gA = A + (size_t)arow * GK + kseg * 8;
    const float* gW = W + (size_t)(bn + prow) * GK + kseg * 8;
    const int off = prow * RPAD + kseg * 4; // u32 index (16B aligned)

    float4 stage[2][4];   // [set][A.lo4, A.hi4, W.lo4, W.hi4]; stage s -> set s&1

    auto ldg_stage = [&](int set, int kt) {
        const int kof = kt * TBK;
        stage[set][0] = *(const float4*)(gA + kof);
        stage[set][1] = *(const float4*)(gA + kof + 4);
        stage[set][2] = *(const float4*)(gW + kof);
        stage[set][3] = *(const float4*)(gW + kof + 4);
    };
    auto pack8 = [&](float4 v0, float4 v1, int buf, int mat) {
        float xs[8] = {v0.x, v0.y, v0.z, v0.w, v1.x, v1.y, v1.z, v1.w};
        uint16_t s0[8], s1[8], s2[8];
        #pragma unroll
        for (int i = 0; i < 8; i++) bsplit(xs[i], s0[i], s1[i], s2[i], S == 3);
        uint4 t0, t1;
        t0.x = (uint32_t)s0[0] | ((uint32_t)s0[1] << 16);
        t0.y = (uint32_t)s0[2] | ((uint32_t)s0[3] << 16);
        t0.z = (uint32_t)s0[4] | ((uint32_t)s0[5] << 16);
        t0.w = (uint32_t)s0[6] | ((uint32_t)s0[7] << 16);
        t1.x = (uint32_t)s1[0] | ((uint32_t)s1[1] << 16);
        t1.y = (uint32_t)s1[2] | ((uint32_t)s1[3] << 16);
        t1.z = (uint32_t)s1[4] | ((uint32_t)s1[5] << 16);
        t1.w = (uint32_t)s1[6] | ((uint32_t)s1[7] << 16);
        *(uint4*)(tbase(buf, mat, 0) + off) = t0;
        *(uint4*)(tbase(buf, mat, 1) + off) = t1;
        if (S == 3) {
            uint4 t2;
            t2.x = (uint32_t)s2[0] | ((uint32_t)s2[1] << 16);
            t2.y = (uint32_t)s2[2] | ((uint32_t)s2[3] << 16);
            t2.z = (uint32_t)s2[4] | ((uint32_t)s2[5] << 16);
            t2.w = (uint32_t)s2[6] | ((uint32_t)s2[7] << 16);
            *(uint4*)(tbase(buf, mat, 2) + off) = t2;
        }
    };
    auto convert_store = [&](int set, int buf) {
        pack8(stage[set][0], stage[set][1], buf, 0);
        pack8(stage[set][2], stage[set][3], buf, 1);
    };

    float acc[4][4][4];
    #pragma unroll
    for (int i = 0; i < 4; i++)
        #pragma unroll
        for (int j = 0; j < 4; j++)
            #pragma unroll
            for (int r = 0; r < 4; r++) acc[i][j][r] = 0.f;

    // ---- prologue: stage0 -> set0 -> buf0; stage1 -> set1 ----
    ldg_stage(0, 0);
    convert_store(0, 0);
    ldg_stage(1, 1);
    __syncthreads();

    for (int kt = 0; kt < KT; ++kt) {
        const int cset = (kt + 1) & 1;                    // stage kt+1 lives in set (kt+1)&1
        if (kt + 1 < KT) convert_store(cset, (kt + 1) & 1);
        if (kt + 2 < KT) ldg_stage(cset ^ 1, kt + 2);     // stage kt+2 -> set (kt+2)&1

        const int buf = kt & 1;
        const uint32_t* at[3]; const uint32_t* bt[3];
        #pragma unroll
        for (int t = 0; t < S; ++t) {
            at[t] = tbase(buf, 0, t) + (wm + gq) * RPAD;
            bt[t] = tbase(buf, 1, t) + (wn + gq) * RPAD;
        }

        // B fragments: S terms x 4 n-tiles
        uint32_t bf[3][4][2];
        #pragma unroll
        for (int t = 0; t < S; ++t)
            #pragma unroll
            for (int nt = 0; nt < 4; ++nt) {
                const uint32_t* bp = bt[t] + nt * 8 * RPAD + tq;
                bf[t][nt][0] = bp[0];
                bf[t][nt][1] = bp[4];
            }
        #pragma unroll
        for (int mt = 0; mt < 4; ++mt) {
            uint32_t af[3][4];
            #pragma unroll
            for (int t = 0; t < S; ++t) {
                const uint32_t* ap = at[t] + mt * 16 * RPAD + tq;
                af[t][0] = ap[0];
                af[t][1] = ap[8 * RPAD];
                af[t][2] = ap[4];
                af[t][3] = ap[8 * RPAD + 4];
            }
            #pragma unroll
            for (int nt = 0; nt < 4; ++nt) {
                // per-tile partial in zero-initialized fragment (small magnitude)
                float d[4] = {0.f, 0.f, 0.f, 0.f};
                mma_bf16(d, af[0], bf[0][nt]);        // 00
                mma_bf16(d, af[0], bf[1][nt]);        // 01
                mma_bf16(d, af[1], bf[0][nt]);        // 10
                if (P == 6) {
                    mma_bf16(d, af[0], bf[2][nt]);    // 02
                    mma_bf16(d, af[2], bf[0][nt]);    // 20
                    mma_bf16(d, af[1], bf[1][nt]);    // 11
                }
                // exact fp32 drain
                acc[mt][nt][0] += d[0];
                acc[mt][nt][1] += d[1];
                acc[mt][nt][2] += d[2];
                acc[mt][nt][3] += d[3];
            }
        }
        __syncthreads();
    }

    // ---- epilogue ----
    #pragma unroll
    for (int mt = 0; mt < 4; ++mt) {
        int r0 = bm + wm + mt * 16 + gq;
        int r1 = r0 + 8;
        #pragma unroll
        for (int nt = 0; nt < 4; ++nt) {
            int c = bn + wn + nt * 8 + tq * 2;
            float b0 = bias ? bias[c]     : 0.f;
            float b1 = bias ? bias[c + 1] : 0.f;
            if (r0 < M) {
                float2 v; v.x = acc[mt][nt][0] + b0; v.y = acc[mt][nt][1] + b1;
                *(float2*)(C + (size_t)r0 * ldc + c) = v;
            }
            if (r1 < M) {
                float2 v; v.x = acc[mt][nt][2] + b0; v.y = acc[mt][nt][3] + b1;
                *(float2*)(C + (size_t)r1 * ldc + c) = v;
            }
        }
    }
}

// ---------------- per-(b,h) |q| / |k| mean scales ----------------
__global__ __launch_bounds__(256) void scales_kernel(const float* __restrict__ qkv)
{
    __shared__ float red[256];
    const int which = blockIdx.x & 1;
    const int bh    = blockIdx.x >> 1;
    const int b = bh / HEADS, h = bh % HEADS;
    const float* base = qkv + (size_t)b * NTOK * CK + which * CDIM + h * HDIM;

    float s = 0.f;
    for (int i = threadIdx.x; i < NTOK * HDIM; i += 256) {
        int n = i >> 6, dd = i & 63;
        s += fabsf(base[(size_t)n * CK + dd]);
    }
    red[threadIdx.x] = s; __syncthreads();
    for (int o = 128; o; o >>= 1) {
        if (threadIdx.x < o) red[threadIdx.x] += red[threadIdx.x + o];
        __syncthreads();
    }
    if (threadIdx.x == 0) {
        float v = red[0] / 12608.0f;
        if (which) g_sk[bh] = v; else g_sq[bh] = v;
    }
}

// ---------------- pack: sign bits for q/k, int8-quantized transposed v ------
__global__ __launch_bounds__(256) void pack_kernel(const float* __restrict__ qkv)
{
    const int bh = blockIdx.x;
    const int b = bh / HEADS, h = bh % HEADS;
    const size_t rowbase = (size_t)b * NTOK * CK + h * HDIM;
    const float* qb_ = qkv + rowbase;
    const float* kb_ = qkv + rowbase + CDIM;
    const float* vb_ = qkv + rowbase + 2 * CDIM;

    for (int n = threadIdx.x; n < NTOK; n += 256) {
        const float* qr = qb_ + (size_t)n * CK;
        const float* kr = kb_ + (size_t)n * CK;
        unsigned long long qm = 0ull, km = 0ull;
        #pragma unroll
        for (int c4 = 0; c4 < 16; c4++) {
            float4 qv = *(const float4*)(qr + c4 * 4);
            float4 kv = *(const float4*)(kr + c4 * 4);
            if (qv.x > 0.f) qm |= 1ull << (c4*4+0);
            if (qv.y > 0.f) qm |= 1ull << (c4*4+1);
            if (qv.z > 0.f) qm |= 1ull << (c4*4+2);
            if (qv.w > 0.f) qm |= 1ull << (c4*4+3);
            if (kv.x > 0.f) km |= 1ull << (c4*4+0);
            if (kv.y > 0.f) km |= 1ull << (c4*4+1);
            if (kv.z > 0.f) km |= 1ull << (c4*4+2);
            if (kv.w > 0.f) km |= 1ull << (c4*4+3);
        }
        g_qb[bh * NTOK + n] = qm;
        g_kb[bh * NTOK + n] = km;
    }

    const float SV = 2.0f / 127.0f;
    for (int i = threadIdx.x; i < HDIM * NW; i += 256) {
        int dd = i / NW, w = i % NW;
        unsigned int word = 0;
        #pragma unroll
        for (int j = 0; j < 4; j++) {
            int m = 4 * w + j;
            int vi = 0;
            if (m < NTOK) {
                float v = vb_[(size_t)m * CK + dd];
                v = fminf(fmaxf(v, -2.f), 2.f);
                float r = rintf(v / SV);
                r = fminf(fmaxf(r, -127.f), 127.f);
                vi = (int)r;
            }
            word |= ((unsigned)vi & 0xFFu) << (8 * j);
        }
        g_vT[(size_t)bh * HDIM * NW + i] = word;
    }
}

// ---------------- fused binary attention ----------------
__global__ __launch_bounds__(256) void attn_kernel(
    const float* __restrict__ rel_table, const int* __restrict__ rel_index,
    float* __restrict__ att)
{
    __shared__ unsigned long long qb_s[NTOK], kb_s[NTOK];
    __shared__ float rel_s[NRD];
    __shared__ unsigned int v_s[HDIM * NW];
    __shared__ __align__(4) unsigned char p_bytes[8 * 224];

    const int bh = blockIdx.x;
    const int b = bh / HEADS, h = bh % HEADS;
    const int tid = threadIdx.x;

    for (int i = tid; i < NTOK; i += 256) {
        qb_s[i] = g_qb[bh * NTOK + i];
        kb_s[i] = g_kb[bh * NTOK + i];
    }
    for (int i = tid; i < NRD; i += 256) rel_s[i] = rel_table[i * HEADS + h];
    for (int i = tid; i < HDIM * NW; i += 256) v_s[i] = g_vT[(size_t)bh * HDIM * NW + i];
    __syncthreads();

    const float sqk = g_sq[bh] * g_sk[bh];
    const float SP  = 1.0f / 255.0f;
    const float OSC = (1.0f / 255.0f) * (2.0f / 127.0f);
    const int warp = tid >> 5, lane = tid & 31;

    for (int n = warp; n < NTOK; n += 8) {
        const unsigned long long qm = qb_s[n];
        const int* ridx = rel_index + n * NTOK;

        float logit[7];
        float mx = -3.0e38f;
        #pragma unroll
        for (int t = 0; t < 7; t++) {
            int m = lane + (t << 5);
            float lg = -3.0e38f;
            if (m < NTOK) {
                int dot = 64 - 2 * __popcll(qm ^ kb_s[m]);
                lg = (sqk * (float)dot) * 0.125f + rel_s[ridx[m]];
            }
            logit[t] = lg;
            mx = fmaxf(mx, lg);
        }
        #pragma unroll
        for (int o = 16; o; o >>= 1) mx = fmaxf(mx, __shfl_xor_sync(0xffffffffu, mx, o));

        float e[7], sum = 0.f;
        #pragma unroll
        for (int t = 0; t < 7; t++) {
            int m = lane + (t << 5);
            e[t] = (m < NTOK) ? expf(logit[t] - mx) : 0.f;
            sum += e[t];
        }
        #pragma unroll
        for (int o = 16; o; o >>= 1) sum += __shfl_xor_sync(0xffffffffu, sum, o);

        unsigned char* pb = p_bytes + warp * 224;
        #pragma unroll
        for (int t = 0; t < 7; t++) {
            int m = lane + (t << 5);
            int pi = 0;
            if (m < NTOK) {
                float p = e[t] / sum;
                float r = rintf(p / SP);
                r = fminf(fmaxf(r, 0.f), 255.f);
                pi = (int)r;
            }
            pb[m] = (unsigned char)pi;
        }
        __syncwarp();

        const unsigned int* pw = (const unsigned int*)pb;
        const unsigned int* v0 = &v_s[lane * NW];
        const unsigned int* v1 = &v_s[(lane + 32) * NW];
        int acc0 = 0, acc1 = 0;
        #pragma unroll
        for (int w = 0; w < NW; w++) {
            unsigned int pword = pw[w];
            acc0 = dp4a_us(pword, v0[w], acc0);
            acc1 = dp4a_us(pword, v1[w], acc1);
        }

        float* orow = att + (size_t)(b * NTOK + n) * CDIM + h * HDIM;
        orow[lane]      = (float)acc0 * OSC;
        orow[lane + 32] = (float)acc1 * OSC;
        __syncwarp();
    }
}

// ---------------- launcher ----------------
extern "C" void kernel_launch(void* const* d_in, const int* in_sizes, int n_in,
                              void* d_out, int out_size)
{
    const float* x         = (const float*)d_in[0];
    const float* qkv_w     = (const float*)d_in[1];
    const float* proj_w    = (const float*)d_in[2];
    const float* proj_b    = (const float*)d_in[3];
    const float* rel_table = (const float*)d_in[4];
    const int*   rel_index = (const int*)d_in[5];
    float* out = (float*)d_out;

    float *qkv_ptr = nullptr, *att_ptr = nullptr;
    cudaGetSymbolAddress((void**)&qkv_ptr, g_qkv);
    cudaGetSymbolAddress((void**)&att_ptr, g_att);

    const int SM3 = 2 * 2 * 3 * TILEU * 4;   // S=3: 73,728 B
    const int SM2 = 2 * 2 * 2 * TILEU * 4;   // S=2: 49,152 B
    cudaFuncSetAttribute(gemm_bf16s<3,6>, cudaFuncAttributeMaxDynamicSharedMemorySize, SM3);
    cudaFuncSetAttribute(gemm_bf16s<2,3>, cudaFuncAttributeMaxDynamicSharedMemorySize, SM2);

    const int GY = (MROWS + TBM - 1) / TBM;  // 99

    // 1) qkv = x @ qkv_w^T  — bf16 3-split, 6 products, fp32 register drain
    dim3 g1(CK / TBN, GY);
    gemm_bf16s<3,6><<<g1, 256, SM3>>>(x, qkv_w, nullptr, qkv_ptr, MROWS, CK);

    // 2) per-(b,h) scales for q,k
    scales_kernel<<<BHT * 2, 256>>>(qkv_ptr);

    // 3) sign-pack q,k; int8-quantize + transpose v
    pack_kernel<<<BHT, 256>>>(qkv_ptr);

    // 4) fused binary attention
    attn_kernel<<<BHT, 256>>>(rel_table, rel_index, att_ptr);

    // 5) out = att @ proj_w^T + proj_b — bf16 2-split, 3 products, fp32 drain
    dim3 g2(CDIM / TBN, GY);
    gemm_bf16s<2,3><<<g2, 256, SM2>>>(att_ptr, proj_w, proj_b, out, MROWS, CDIM);
}

// round 11
// speedup vs baseline: 1.1593x; 1.1593x over previous
#include <cuda_runtime.h>
#include <cuda_fp16.h>
#include <cstdint>

// ---------------- problem constants ----------------
#define BATCH 64
#define NTOK  197
#define HEADS 12
#define HDIM  64
#define CDIM  768
#define CK    2304
#define MROWS (BATCH*NTOK) // 12608
#define NRD   732
#define NW    50
#define BHT   (BATCH*HEADS)

// ---------------- device scratch (cudaMalloc is banned) -------------
__device__ float              g_qkv[(size_t)MROWS * CK];
__device__ float              g_att[(size_t)MROWS * CDIM];
__device__ float              g_sq[BHT];
__device__ float              g_sk[BHT];
__device__ unsigned long long g_qb[BHT * NTOK];
__device__ unsigned long long g_kb[BHT * NTOK];
__device__ unsigned int       g_vT[(size_t)BHT * HDIM * NW];

// ---------------- small helpers ----------------
__device__ __forceinline__ int dp4a_us(unsigned int a, unsigned int b, int c) {
    int d; asm("dp4a.u32.s32 %0, %1, %2, %3;" : "=r"(d) : "r"(a), "r"(b), "r"(c));
    return d;
}
__device__ __forceinline__ void mma_f16(float* c, const uint32_t* a, const uint32_t* b) {
    asm volatile(
        "mma.sync.aligned.m16n8k16.row.col.f32.f16.f16.f32 "
        "{%0,%1,%2,%3}, {%4,%5,%6,%7}, {%8,%9}, {%0,%1,%2,%3};"
        : "+f"(c[0]), "+f"(c[1]), "+f"(c[2]), "+f"(c[3])
        : "r"(a[0]), "r"(a[1]), "r"(a[2]), "r"(a[3]), "r"(b[0]), "r"(b[1]));
}
// Exponent-compensated fp16 2-way splits (all terms normal-range; the R9
// subnormal-flush hazard is eliminated by the 2^11 / 2^5 scalings):
//   A (x ~ O(1)):   x    = a0 + a1*2^-11 + O(2^-22 x)
//   W (w ~ 0.02):   32*w = b0 + b1*2^-11 + O(2^-22 *32w)
// so x*w = 2^-5*a0b0 + 2^-16*(a0b1 + a1b0) + 2^-27*a1b1 + O(2^-22 xw).
__device__ __forceinline__ void hsplitA(float x, uint16_t& s0, uint16_t& s1) {
    __half h0 = __float2half_rn(x);
    __half h1 = __float2half_rn((x - __half2float(h0)) * 2048.0f);
    s0 = *reinterpret_cast<uint16_t*>(&h0);
    s1 = *reinterpret_cast<uint16_t*>(&h1);
}
__device__ __forceinline__ void hsplitB(float w, uint16_t& s0, uint16_t& s1) {
    float ws = w * 32.0f;
    __half h0 = __float2half_rn(ws);
    __half h1 = __float2half_rn((ws - __half2float(h0)) * 2048.0f);
    s0 = *reinterpret_cast<uint16_t*>(&h0);
    s1 = *reinterpret_cast<uint16_t*>(&h1);
}

#define SC_HH 0.03125f                    // 2^-5
#define SC_C  1.52587890625e-05f          // 2^-16
#define SC_2  7.450580596923828e-09f      // 2^-27

// ====== compensated-fp16 mma.sync GEMM, fp32 register drain (R8 scheme) =====
// C[M,N] = A[M,768] @ W[N,768]^T (+bias), leading dim ldc.
// P = 3: products 00, 01+10       (V / proj paths)
// P = 4: + 11 at scale 2^-27      (flip-critical QK path, R8-parity error)
// Per k-tile: hh product into zero-init fragment, corrections chained into a
// second zero-init fragment, both drained to fp32 registers with exact-pow2
// FFMAs — long-range accumulation never touches the weak mma C-path.
#define GK      768
#define TBM     128
#define TBN     128
#define TBK     16
#define KT      (GK / TBK)          // 48
#define RPAD    12                  // u32 per smem row (8 data + 4 pad)
#define TILEU   (128 * RPAD)        // u32 per tile
#define GSMEM   (2 * 2 * 2 * TILEU * 4)   // 49,152 B

template<int P>
__global__ void __launch_bounds__(256, 1) gemm_f16c(
    const float* __restrict__ A, const float* __restrict__ W,
    const float* __restrict__ bias, float* __restrict__ C,
    int M, int ldc)
{
    extern __shared__ uint32_t smu[];
    auto tbase = [&](int buf, int mat, int t) -> uint32_t* {
        return smu + (size_t)(((buf * 2 + mat) * 2) + t) * TILEU;
    };

    const int tid  = threadIdx.x;
    const int wid  = tid >> 5;
    const int lane = tid & 31;
    const int gq   = lane >> 2;             // 0..7
    const int tq   = lane & 3;              // 0..3
    const int bm = blockIdx.y * TBM;
    const int bn = blockIdx.x * TBN;
    const int wm = (wid >> 2) * 64;
    const int wn = (wid & 3) * 32;

    // ---- producer mapping: 1 row x 8 k-floats per matrix per thread ----
    const int prow = tid >> 1;              // 0..127
    const int kseg = tid & 1;               // 0/1 -> k offset 0/8
    int arow = bm + prow; if (arow >= M) arow = M - 1;
    const float* gA = A + (size_t)arow * GK + kseg * 8;
    const float* gW = W + (size_t)(bn + prow) * GK + kseg * 8;
    const int off = prow * RPAD + kseg * 4; // u32 index (16B aligned)

    float4 stage[2][4];   // [set][A.lo4, A.hi4, W.lo4, W.hi4]; stage s -> set s&1

    auto ldg_stage = [&](int set, int kt) {
        const int kof = kt * TBK;
        stage[set][0] = *(const float4*)(gA + kof);
        stage[set][1] = *(const float4*)(gA + kof + 4);
        stage[set][2] = *(const float4*)(gW + kof);
        stage[set][3] = *(const float4*)(gW + kof + 4);
    };
    auto pack8 = [&](float4 v0, float4 v1, int buf, int mat) {
        float xs[8] = {v0.x, v0.y, v0.z, v0.w, v1.x, v1.y, v1.z, v1.w};
        uint16_t s0[8], s1[8];
        #pragma unroll
        for (int i = 0; i < 8; i++) {
            if (mat == 0) hsplitA(xs[i], s0[i], s1[i]);
            else          hsplitB(xs[i], s0[i], s1[i]);
        }
        uint4 t0, t1;
        t0.x = (uint32_t)s0[0] | ((uint32_t)s0[1] << 16);
        t0.y = (uint32_t)s0[2] | ((uint32_t)s0[3] << 16);
        t0.z = (uint32_t)s0[4] | ((uint32_t)s0[5] << 16);
        t0.w = (uint32_t)s0[6] | ((uint32_t)s0[7] << 16);
        t1.x = (uint32_t)s1[0] | ((uint32_t)s1[1] << 16);
        t1.y = (uint32_t)s1[2] | ((uint32_t)s1[3] << 16);
        t1.z = (uint32_t)s1[4] | ((uint32_t)s1[5] << 16);
        t1.w = (uint32_t)s1[6] | ((uint32_t)s1[7] << 16);
        *(uint4*)(tbase(buf, mat, 0) + off) = t0;
        *(uint4*)(tbase(buf, mat, 1) + off) = t1;
    };
    auto convert_store = [&](int set, int buf) {
        pack8(stage[set][0], stage[set][1], buf, 0);
        pack8(stage[set][2], stage[set][3], buf, 1);
    };

    float acc[4][4][4];
    #pragma unroll
    for (int i = 0; i < 4; i++)
        #pragma unroll
        for (int j = 0; j < 4; j++)
            #pragma unroll
            for (int r = 0; r < 4; r++) acc[i][j][r] = 0.f;

    // ---- prologue: stage0 -> set0 -> buf0; stage1 -> set1 ----
    ldg_stage(0, 0);
    convert_store(0, 0);
    ldg_stage(1, 1);
    __syncthreads();

    for (int kt = 0; kt < KT; ++kt) {
        const int cset = (kt + 1) & 1;                    // stage kt+1 lives in set (kt+1)&1
        if (kt + 1 < KT) convert_store(cset, (kt + 1) & 1);
        if (kt + 2 < KT) ldg_stage(cset ^ 1, kt + 2);     // stage kt+2 -> set (kt+2)&1

        const int buf = kt & 1;
        const uint32_t* at[2]; const uint32_t* bt[2];
        #pragma unroll
        for (int t = 0; t < 2; ++t) {
            at[t] = tbase(buf, 0, t) + (wm + gq) * RPAD;
            bt[t] = tbase(buf, 1, t) + (wn + gq) * RPAD;
        }

        // B fragments: 2 terms x 4 n-tiles
        uint32_t bf[2][4][2];
        #pragma unroll
        for (int t = 0; t < 2; ++t)
            #pragma unroll
            for (int nt = 0; nt < 4; ++nt) {
                const uint32_t* bp = bt[t] + nt * 8 * RPAD + tq;
                bf[t][nt][0] = bp[0];
                bf[t][nt][1] = bp[4];
            }
        #pragma unroll
        for (int mt = 0; mt < 4; ++mt) {
            uint32_t af[2][4];
            #pragma unroll
            for (int t = 0; t < 2; ++t) {
                const uint32_t* ap = at[t] + mt * 16 * RPAD + tq;
                af[t][0] = ap[0];
                af[t][1] = ap[8 * RPAD];
                af[t][2] = ap[4];
                af[t][3] = ap[8 * RPAD + 4];
            }
            #pragma unroll
            for (int nt = 0; nt < 4; ++nt) {
                // zero-init fragments: partials stay small, so the mma C-path's
                // reduced-precision accumulate only rounds small values.
                float dh[4] = {0.f, 0.f, 0.f, 0.f};
                mma_f16(dh, af[0], bf[0][nt]);            // 00  (scale 2^-5)
                float dc[4] = {0.f, 0.f, 0.f, 0.f};
                mma_f16(dc, af[0], bf[1][nt]);            // 01  (scale 2^-16)
                mma_f16(dc, af[1], bf[0][nt]);            // 10  (scale 2^-16)
                float d2[4] = {0.f, 0.f, 0.f, 0.f};
                if (P == 4)
                    mma_f16(d2, af[1], bf[1][nt]);        // 11  (scale 2^-27)
                #pragma unroll
                for (int r = 0; r < 4; ++r) {
                    float a = acc[mt][nt][r];
                    a = fmaf(dh[r], SC_HH, a);            // exact-pow2 drains
                    a = fmaf(dc[r], SC_C, a);
                    if (P == 4) a = fmaf(d2[r], SC_2, a);
                    acc[mt][nt][r] = a;
                }
            }
        }
        __syncthreads();
    }

    // ---- epilogue ----
    #pragma unroll
    for (int mt = 0; mt < 4; ++mt) {
        int r0 = bm + wm + mt * 16 + gq;
        int r1 = r0 + 8;
        #pragma unroll
        for (int nt = 0; nt < 4; ++nt) {
            int c = bn + wn + nt * 8 + tq * 2;
            float b0 = bias ? bias[c]     : 0.f;
            float b1 = bias ? bias[c + 1] : 0.f;
            if (r0 < M) {
                float2 v; v.x = acc[mt][nt][0] + b0; v.y = acc[mt][nt][1] + b1;
                *(float2*)(C + (size_t)r0 * ldc + c) = v;
            }
            if (r1 < M) {
                float2 v; v.x = acc[mt][nt][2] + b0; v.y = acc[mt][nt][3] + b1;
                *(float2*)(C + (size_t)r1 * ldc + c) = v;
            }
        }
    }
}

// ---------------- per-(b,h) |q| / |k| mean scales ----------------
__global__ __launch_bounds__(256) void scales_kernel(const float* __restrict__ qkv)
{
    __shared__ float red[256];
    const int which = blockIdx.x & 1;
    const int bh    = blockIdx.x >> 1;
    const int b = bh / HEADS, h = bh % HEADS;
    const float* base = qkv + (size_t)b * NTOK * CK + which * CDIM + h * HDIM;

    float s = 0.f;
    for (int i = threadIdx.x; i < NTOK * HDIM; i += 256) {
        int n = i >> 6, dd = i & 63;
        s += fabsf(base[(size_t)n * CK + dd]);
    }
    red[threadIdx.x] = s; __syncthreads();
    for (int o = 128; o; o >>= 1) {
        if (threadIdx.x < o) red[threadIdx.x] += red[threadIdx.x + o];
        __syncthreads();
    }
    if (threadIdx.x == 0) {
        float v = red[0] / 12608.0f;
        if (which) g_sk[bh] = v; else g_sq[bh] = v;
    }
}

// ---------------- pack: sign bits for q/k, int8-quantized transposed v ------
__global__ __launch_bounds__(256) void pack_kernel(const float* __restrict__ qkv)
{
    const int bh = blockIdx.x;
    const int b = bh / HEADS, h = bh % HEADS;
    const size_t rowbase = (size_t)b * NTOK * CK + h * HDIM;
    const float* qb_ = qkv + rowbase;
    const float* kb_ = qkv + rowbase + CDIM;
    const float* vb_ = qkv + rowbase + 2 * CDIM;

    for (int n = threadIdx.x; n < NTOK; n += 256) {
        const float* qr = qb_ + (size_t)n * CK;
        const float* kr = kb_ + (size_t)n * CK;
        unsigned long long qm = 0ull, km = 0ull;
        #pragma unroll
        for (int c4 = 0; c4 < 16; c4++) {
            float4 qv = *(const float4*)(qr + c4 * 4);
            float4 kv = *(const float4*)(kr + c4 * 4);
            if (qv.x > 0.f) qm |= 1ull << (c4*4+0);
            if (qv.y > 0.f) qm |= 1ull << (c4*4+1);
            if (qv.z > 0.f) qm |= 1ull << (c4*4+2);
            if (qv.w > 0.f) qm |= 1ull << (c4*4+3);
            if (kv.x > 0.f) km |= 1ull << (c4*4+0);
            if (kv.y > 0.f) km |= 1ull << (c4*4+1);
            if (kv.z > 0.f) km |= 1ull << (c4*4+2);
            if (kv.w > 0.f) km |= 1ull << (c4*4+3);
        }
        g_qb[bh * NTOK + n] = qm;
        g_kb[bh * NTOK + n] = km;
    }

    const float SV = 2.0f / 127.0f;
    for (int i = threadIdx.x; i < HDIM * NW; i += 256) {
        int dd = i / NW, w = i % NW;
        unsigned int word = 0;
        #pragma unroll
        for (int j = 0; j < 4; j++) {
            int m = 4 * w + j;
            int vi = 0;
            if (m < NTOK) {
                float v = vb_[(size_t)m * CK + dd];
                v = fminf(fmaxf(v, -2.f), 2.f);
                float r = rintf(v / SV);
                r = fminf(fmaxf(r, -127.f), 127.f);
                vi = (int)r;
            }
            word |= ((unsigned)vi & 0xFFu) << (8 * j);
        }
        g_vT[(size_t)bh * HDIM * NW + i] = word;
    }
}

// ---------------- fused binary attention ----------------
__global__ __launch_bounds__(256) void attn_kernel(
    const float* __restrict__ rel_table, const int* __restrict__ rel_index,
    float* __restrict__ att)
{
    __shared__ unsigned long long qb_s[NTOK], kb_s[NTOK];
    __shared__ float rel_s[NRD];
    __shared__ unsigned int v_s[HDIM * NW];
    __shared__ __align__(4) unsigned char p_bytes[8 * 224];

    const int bh = blockIdx.x;
    const int b = bh / HEADS, h = bh % HEADS;
    const int tid = threadIdx.x;

    for (int i = tid; i < NTOK; i += 256) {
        qb_s[i] = g_qb[bh * NTOK + i];
        kb_s[i] = g_kb[bh * NTOK + i];
    }
    for (int i = tid; i < NRD; i += 256) rel_s[i] = rel_table[i * HEADS + h];
    for (int i = tid; i < HDIM * NW; i += 256) v_s[i] = g_vT[(size_t)bh * HDIM * NW + i];
    __syncthreads();

    const float sqk = g_sq[bh] * g_sk[bh];
    const float SP  = 1.0f / 255.0f;
    const float OSC = (1.0f / 255.0f) * (2.0f / 127.0f);
    const int warp = tid >> 5, lane = tid & 31;

    for (int n = warp; n < NTOK; n += 8) {
        const unsigned long long qm = qb_s[n];
        const int* ridx = rel_index + n * NTOK;

        float logit[7];
        float mx = -3.0e38f;
        #pragma unroll
        for (int t = 0; t < 7; t++) {
            int m = lane + (t << 5);
            float lg = -3.0e38f;
            if (m < NTOK) {
                int dot = 64 - 2 * __popcll(qm ^ kb_s[m]);
                lg = (sqk * (float)dot) * 0.125f + rel_s[ridx[m]];
            }
            logit[t] = lg;
            mx = fmaxf(mx, lg);
        }
        #pragma unroll
        for (int o = 16; o; o >>= 1) mx = fmaxf(mx, __shfl_xor_sync(0xffffffffu, mx, o));

        float e[7], sum = 0.f;
        #pragma unroll
        for (int t = 0; t < 7; t++) {
            int m = lane + (t << 5);
            e[t] = (m < NTOK) ? expf(logit[t] - mx) : 0.f;
            sum += e[t];
        }
        #pragma unroll
        for (int o = 16; o; o >>= 1) sum += __shfl_xor_sync(0xffffffffu, sum, o);

        unsigned char* pb = p_bytes + warp * 224;
        #pragma unroll
        for (int t = 0; t < 7; t++) {
            int m = lane + (t << 5);
            int pi = 0;
            if (m < NTOK) {
                float p = e[t] / sum;
                float r = rintf(p / SP);
                r = fminf(fmaxf(r, 0.f), 255.f);
                pi = (int)r;
            }
            pb[m] = (unsigned char)pi;
        }
        __syncwarp();

        const unsigned int* pw = (const unsigned int*)pb;
        const unsigned int* v0 = &v_s[lane * NW];
        const unsigned int* v1 = &v_s[(lane + 32) * NW];
        int acc0 = 0, acc1 = 0;
        #pragma unroll
        for (int w = 0; w < NW; w++) {
            unsigned int pword = pw[w];
            acc0 = dp4a_us(pword, v0[w], acc0);
            acc1 = dp4a_us(pword, v1[w], acc1);
        }

        float* orow = att + (size_t)(b * NTOK + n) * CDIM + h * HDIM;
        orow[lane]      = (float)acc0 * OSC;
        orow[lane + 32] = (float)acc1 * OSC;
        __syncwarp();
    }
}

// ---------------- launcher ----------------
extern "C" void kernel_launch(void* const* d_in, const int* in_sizes, int n_in,
                              void* d_out, int out_size)
{
    const float* x         = (const float*)d_in[0];
    const float* qkv_w     = (const float*)d_in[1];
    const float* proj_w    = (const float*)d_in[2];
    const float* proj_b    = (const float*)d_in[3];
    const float* rel_table = (const float*)d_in[4];
    const int*   rel_index = (const int*)d_in[5];
    float* out = (float*)d_out;

    float *qkv_ptr = nullptr, *att_ptr = nullptr;
    cudaGetSymbolAddress((void**)&qkv_ptr, g_qkv);
    cudaGetSymbolAddress((void**)&att_ptr, g_att);

    cudaFuncSetAttribute(gemm_f16c<3>, cudaFuncAttributeMaxDynamicSharedMemorySize, GSMEM);
    cudaFuncSetAttribute(gemm_f16c<4>, cudaFuncAttributeMaxDynamicSharedMemorySize, GSMEM);

    const int GY = (MROWS + TBM - 1) / TBM;  // 99

    // 1a) qkv Q,K columns [0,1536): P=4 (R8-parity error on the flip-critical path)
    dim3 gqk(1536 / TBN, GY);
    gemm_f16c<4><<<gqk, 256, GSMEM>>>(x, qkv_w, nullptr, qkv_ptr, MROWS, CK);

    // 1b) qkv V columns [1536,2304): P=3 (budget proven by R2 at ~9e-7)
    dim3 gv(768 / TBN, GY);
    gemm_f16c<3><<<gv, 256, GSMEM>>>(x, qkv_w + (size_t)1536 * GK, nullptr,
                                     qkv_ptr + 1536, MROWS, CK);

    // 2) per-(b,h) scales for q,k
    scales_kernel<<<BHT * 2, 256>>>(qkv_ptr);

    // 3) sign-pack q,k; int8-quantize + transpose v
    pack_kernel<<<BHT, 256>>>(qkv_ptr);

    // 4) fused binary attention
    attn_kernel<<<BHT, 256>>>(rel_table, rel_index, att_ptr);

    // 5) out = att @ proj_w^T + proj_b: P=3 (no quantizer downstream)
    dim3 gp(CDIM / TBN, GY);
    gemm_f16c<3><<<gp, 256, GSMEM>>>(att_ptr, proj_w, proj_b, out, MROWS, CDIM);
}